// round 1
// baseline (speedup 1.0000x reference)
#include <cuda_runtime.h>
#include <math.h>
#include <stdint.h>

#define MAXN 16
#define HDIM 64
#define DDIM 64
#define HID 40
#define BMAX 65536

// ---------------- scratch (no allocations allowed) ----------------
__device__ float g_pe[MAXN * HDIM];   // positional codes [16][64]
__device__ int   g_n[BMAX];           // per-row argmax

__device__ __forceinline__ float gelu_tanh(float x) {
    // jax.nn.gelu default (approximate=True)
    float x3 = x * x * x;
    float t = tanhf(0.7978845608028654f * (x + 0.044715f * x3));
    return 0.5f * x * (1.0f + t);
}

// ---------------- packed f32x2 helpers ----------------
#define FMA2(acc, a2, b2v) \
    asm("fma.rn.f32x2 %0, %1, %2, %0;" : "+l"(acc) : "l"(a2), "l"(b2v))

__device__ __forceinline__ unsigned long long splat2(float a) {
    unsigned long long r;
    unsigned int u = __float_as_uint(a);
    asm("mov.b64 %0, {%1, %1};" : "=l"(r) : "r"(u));
    return r;
}
__device__ __forceinline__ void unpack2(unsigned long long v, float& lo, float& hi) {
    unsigned int u0, u1;
    asm("mov.b64 {%0, %1}, %2;" : "=r"(u0), "=r"(u1) : "l"(v));
    lo = __uint_as_float(u0);
    hi = __uint_as_float(u1);
}

// ================= kernel P: pe = MLP(eye(16)) =================
// one-hot input => hidden[p][j] = gelu(pe_w1[p][j] + b1[j])
__global__ void pe_kernel(const float* __restrict__ w1, const float* __restrict__ b1,
                          const float* __restrict__ w2, const float* __restrict__ b2) {
    __shared__ float h[MAXN * HID];
    int tid = threadIdx.x;
    for (int i = tid; i < MAXN * HID; i += blockDim.x) {
        int j = i % HID;
        h[i] = gelu_tanh(w1[i] + b1[j]);
    }
    __syncthreads();
    for (int i = tid; i < MAXN * HDIM; i += blockDim.x) {
        int p = i / HDIM, d = i % HDIM;
        float acc = b2[d];
        #pragma unroll
        for (int j = 0; j < HID; j++) acc += h[p * HID + j] * w2[j * HDIM + d];
        g_pe[i] = acc;
    }
}

// ================= kernel A: size MLP + argmax + mask/batch/n_pred =================
#define SP_ROWS 128
__global__ void __launch_bounds__(SP_ROWS) sp_kernel(
    const float* __restrict__ z,
    const float* __restrict__ w1, const float* __restrict__ b1,
    const float* __restrict__ w2, const float* __restrict__ b2,
    float* __restrict__ out_npred, float* __restrict__ out_mask,
    float* __restrict__ out_batch) {
    __shared__ float zs[SP_ROWS][68];        // padded to break bank conflicts
    __shared__ float w1s[HDIM * HID];        // [k][j]
    __shared__ float w2s[HID * MAXN];        // [j][p]
    __shared__ float b1s[HID];
    __shared__ float b2s[MAXN];

    int tid = threadIdx.x;
    int row0 = blockIdx.x * SP_ROWS;

    for (int i = tid; i < HDIM * HID; i += SP_ROWS) w1s[i] = w1[i];
    for (int i = tid; i < HID * MAXN; i += SP_ROWS) w2s[i] = w2[i];
    if (tid < HID)  b1s[tid] = b1[tid];
    if (tid < MAXN) b2s[tid] = b2[tid];
    // coalesced stage of z rows
    for (int i = tid; i < SP_ROWS * (HDIM / 4); i += SP_ROWS) {
        int r = i / (HDIM / 4), c4 = i % (HDIM / 4);
        float4 v = ((const float4*)(z + (size_t)(row0 + r) * HDIM))[c4];
        *(float4*)&zs[r][c4 * 4] = v;
    }
    __syncthreads();

    int b = row0 + tid;

    float h[HID];
    #pragma unroll
    for (int j4 = 0; j4 < HID / 4; j4++) {
        float4 bv = *(const float4*)&b1s[j4 * 4];
        h[j4 * 4 + 0] = bv.x; h[j4 * 4 + 1] = bv.y;
        h[j4 * 4 + 2] = bv.z; h[j4 * 4 + 3] = bv.w;
    }
    for (int k = 0; k < HDIM; k++) {
        float zk = zs[tid][k];
        const float4* wr = (const float4*)&w1s[k * HID];
        #pragma unroll
        for (int j4 = 0; j4 < HID / 4; j4++) {
            float4 w = wr[j4];
            h[j4 * 4 + 0] += zk * w.x;
            h[j4 * 4 + 1] += zk * w.y;
            h[j4 * 4 + 2] += zk * w.z;
            h[j4 * 4 + 3] += zk * w.w;
        }
    }
    float o[MAXN];
    #pragma unroll
    for (int p4 = 0; p4 < MAXN / 4; p4++) {
        float4 bv = *(const float4*)&b2s[p4 * 4];
        o[p4 * 4 + 0] = bv.x; o[p4 * 4 + 1] = bv.y;
        o[p4 * 4 + 2] = bv.z; o[p4 * 4 + 3] = bv.w;
    }
    #pragma unroll
    for (int j = 0; j < HID; j++) {
        float hj = gelu_tanh(h[j]);
        const float4* wr = (const float4*)&w2s[j * MAXN];
        #pragma unroll
        for (int p4 = 0; p4 < MAXN / 4; p4++) {
            float4 w = wr[p4];
            o[p4 * 4 + 0] += hj * w.x;
            o[p4 * 4 + 1] += hj * w.y;
            o[p4 * 4 + 2] += hj * w.z;
            o[p4 * 4 + 3] += hj * w.w;
        }
    }
    // argmax, first-max tiebreak (matches jnp.argmax)
    int n = 0; float best = o[0];
    #pragma unroll
    for (int p = 1; p < MAXN; p++) {
        if (o[p] > best) { best = o[p]; n = p; }
    }
    g_n[b] = n;

    size_t base = (size_t)b * MAXN;
    #pragma unroll
    for (int p4 = 0; p4 < MAXN / 4; p4++) {
        *(float4*)(out_npred + base + p4 * 4) =
            make_float4(o[p4 * 4 + 0], o[p4 * 4 + 1], o[p4 * 4 + 2], o[p4 * 4 + 3]);
    }
    float fb = (float)b;
    #pragma unroll
    for (int p4 = 0; p4 < MAXN / 4; p4++) {
        float4 mv;
        mv.x = (p4 * 4 + 0 < n) ? 1.0f : 0.0f;
        mv.y = (p4 * 4 + 1 < n) ? 1.0f : 0.0f;
        mv.z = (p4 * 4 + 2 < n) ? 1.0f : 0.0f;
        mv.w = (p4 * 4 + 3 < n) ? 1.0f : 0.0f;
        *(float4*)(out_mask + base + p4 * 4) = mv;
        *(float4*)(out_batch + base + p4 * 4) = make_float4(fb, fb, fb, fb);
    }
}

// ================= kernel B: fused decoder MLP (two GEMMs) =================
// M-tile = 128 rows of the (B*16)x64 problem (8 z-rows x 16 positions),
// 128 threads, each computing an 8x8 output tile with packed f32x2 FMAs.
#define BM 128
#define LDA 68
#define DEC_THREADS 128

// smem layout (floats)
#define OFF_W1 0
#define OFF_W2 (OFF_W1 + 64 * 64)
#define OFF_A  (OFF_W2 + 64 * 64)
#define OFF_H  (OFF_A + BM * LDA)
#define OFF_B1 (OFF_H + BM * LDA)
#define OFF_B2 (OFF_B1 + 64)
#define OFF_Z  (OFF_B2 + 64)
#define OFF_PE (OFF_Z + 8 * 64)
#define OFF_NS (OFF_PE + MAXN * 64)
#define DEC_SMEM_FLOATS (OFF_NS + 8)
#define DEC_SMEM_BYTES (DEC_SMEM_FLOATS * 4)

__device__ __forceinline__ void gemm_tile8x8(
    const float* __restrict__ Asm, const float* __restrict__ Bsm,
    int m0, int n0, unsigned long long (&acc2)[8][4]) {
    #pragma unroll 4
    for (int kc = 0; kc < 64; kc += 4) {
        float4 a[8];
        #pragma unroll
        for (int i = 0; i < 8; i++)
            a[i] = *(const float4*)(Asm + (m0 + i) * LDA + kc);
        #pragma unroll
        for (int kk = 0; kk < 4; kk++) {
            ulonglong2 blo = *(const ulonglong2*)(Bsm + (kc + kk) * 64 + n0);
            ulonglong2 bhi = *(const ulonglong2*)(Bsm + (kc + kk) * 64 + n0 + 4);
            #pragma unroll
            for (int i = 0; i < 8; i++) {
                float av = (kk == 0) ? a[i].x : (kk == 1) ? a[i].y
                         : (kk == 2) ? a[i].z : a[i].w;
                unsigned long long a2 = splat2(av);
                FMA2(acc2[i][0], a2, blo.x);
                FMA2(acc2[i][1], a2, blo.y);
                FMA2(acc2[i][2], a2, bhi.x);
                FMA2(acc2[i][3], a2, bhi.y);
            }
        }
    }
}

__global__ void __launch_bounds__(DEC_THREADS, 2) dec_kernel(
    const float* __restrict__ z,
    const float* __restrict__ w1, const float* __restrict__ b1,
    const float* __restrict__ w2, const float* __restrict__ b2,
    float* __restrict__ out_x) {
    extern __shared__ __align__(16) float smem[];
    float* W1s = smem + OFF_W1;
    float* W2s = smem + OFF_W2;
    float* As  = smem + OFF_A;
    float* Hs  = smem + OFF_H;
    float* b1s = smem + OFF_B1;
    float* b2s = smem + OFF_B2;
    float* zs  = smem + OFF_Z;
    float* pes = smem + OFF_PE;
    int*   ns  = (int*)(smem + OFF_NS);

    int tid = threadIdx.x;
    int m_base = blockIdx.x * BM;        // row in [0, B*16)
    int zrow0 = m_base / MAXN;           // 8 consecutive z rows

    // ---- prologue loads ----
    for (int i = tid; i < 64 * 64; i += DEC_THREADS) {
        W1s[i] = w1[i];
        W2s[i] = w2[i];
    }
    if (tid < 64) { b1s[tid] = b1[tid]; b2s[tid] = b2[tid]; }
    for (int i = tid; i < 8 * 64 / 4; i += DEC_THREADS)
        ((float4*)zs)[i] = ((const float4*)(z + (size_t)zrow0 * HDIM))[i];
    for (int i = tid; i < MAXN * 64 / 4; i += DEC_THREADS)
        ((float4*)pes)[i] = ((const float4*)g_pe)[i];
    if (tid < 8) ns[tid] = g_n[zrow0 + tid];
    __syncthreads();

    // ---- build A = zp tile: As[m][k] = z[m/16][k] * pe[m%16][k] ----
    for (int i = tid; i < BM * 64 / 4; i += DEC_THREADS) {
        int m = (i * 4) / 64;
        int k = (i * 4) % 64;
        int zr = m >> 4, p = m & 15;
        float4 zv = *(const float4*)&zs[zr * 64 + k];
        float4 pv = *(const float4*)&pes[p * 64 + k];
        *(float4*)&As[m * LDA + k] =
            make_float4(zv.x * pv.x, zv.y * pv.y, zv.z * pv.z, zv.w * pv.w);
    }
    __syncthreads();

    int n_group = tid & 7;
    int m_group = tid >> 3;
    int n0 = n_group * 8;
    int m0 = m_group * 8;

    // ---- GEMM1: H = gelu(A @ W1 + b1) ----
    {
        unsigned long long acc2[8][4];
        #pragma unroll
        for (int i = 0; i < 8; i++)
            #pragma unroll
            for (int j = 0; j < 4; j++) acc2[i][j] = 0ull;
        gemm_tile8x8(As, W1s, m0, n0, acc2);

        #pragma unroll
        for (int i = 0; i < 8; i++) {
            float v[8];
            #pragma unroll
            for (int j = 0; j < 4; j++) unpack2(acc2[i][j], v[2 * j], v[2 * j + 1]);
            float4 lo, hi;
            lo.x = gelu_tanh(v[0] + b1s[n0 + 0]);
            lo.y = gelu_tanh(v[1] + b1s[n0 + 1]);
            lo.z = gelu_tanh(v[2] + b1s[n0 + 2]);
            lo.w = gelu_tanh(v[3] + b1s[n0 + 3]);
            hi.x = gelu_tanh(v[4] + b1s[n0 + 4]);
            hi.y = gelu_tanh(v[5] + b1s[n0 + 5]);
            hi.z = gelu_tanh(v[6] + b1s[n0 + 6]);
            hi.w = gelu_tanh(v[7] + b1s[n0 + 7]);
            *(float4*)&Hs[(m0 + i) * LDA + n0] = lo;
            *(float4*)&Hs[(m0 + i) * LDA + n0 + 4] = hi;
        }
    }
    __syncthreads();

    // ---- GEMM2: X = H @ W2 + b2, mask, store ----
    {
        unsigned long long acc2[8][4];
        #pragma unroll
        for (int i = 0; i < 8; i++)
            #pragma unroll
            for (int j = 0; j < 4; j++) acc2[i][j] = 0ull;
        gemm_tile8x8(Hs, W2s, m0, n0, acc2);

        #pragma unroll
        for (int i = 0; i < 8; i++) {
            int m = m0 + i;
            int p = m & 15;
            bool valid = p < ns[m >> 4];
            float v[8];
            #pragma unroll
            for (int j = 0; j < 4; j++) unpack2(acc2[i][j], v[2 * j], v[2 * j + 1]);
            float4 lo, hi;
            lo.x = valid ? (v[0] + b2s[n0 + 0]) : 0.0f;
            lo.y = valid ? (v[1] + b2s[n0 + 1]) : 0.0f;
            lo.z = valid ? (v[2] + b2s[n0 + 2]) : 0.0f;
            lo.w = valid ? (v[3] + b2s[n0 + 3]) : 0.0f;
            hi.x = valid ? (v[4] + b2s[n0 + 4]) : 0.0f;
            hi.y = valid ? (v[5] + b2s[n0 + 5]) : 0.0f;
            hi.z = valid ? (v[6] + b2s[n0 + 6]) : 0.0f;
            hi.w = valid ? (v[7] + b2s[n0 + 7]) : 0.0f;
            size_t gbase = (size_t)(m_base + m) * DDIM + n0;
            *(float4*)(out_x + gbase) = lo;
            *(float4*)(out_x + gbase + 4) = hi;
        }
    }
}

// ================= launch =================
extern "C" void kernel_launch(void* const* d_in, const int* in_sizes, int n_in,
                              void* d_out, int out_size) {
    const float* z      = (const float*)d_in[0];
    const float* sp_w1  = (const float*)d_in[1];
    const float* sp_b1  = (const float*)d_in[2];
    const float* sp_w2  = (const float*)d_in[3];
    const float* sp_b2  = (const float*)d_in[4];
    const float* pe_w1  = (const float*)d_in[5];
    const float* pe_b1  = (const float*)d_in[6];
    const float* pe_w2  = (const float*)d_in[7];
    const float* pe_b2  = (const float*)d_in[8];
    const float* dec_w1 = (const float*)d_in[9];
    const float* dec_b1 = (const float*)d_in[10];
    const float* dec_w2 = (const float*)d_in[11];
    const float* dec_b2 = (const float*)d_in[12];

    int B = in_sizes[0] / HDIM;   // 65536

    float* out = (float*)d_out;
    float* out_x     = out;                                   // [B,16,64]
    float* out_mask  = out_x + (size_t)B * MAXN * DDIM;       // [B,16]
    float* out_batch = out_mask + (size_t)B * MAXN;           // [B,16]
    float* out_npred = out_batch + (size_t)B * MAXN;          // [B,16]

    pe_kernel<<<1, 256>>>(pe_w1, pe_b1, pe_w2, pe_b2);
    sp_kernel<<<B / SP_ROWS, SP_ROWS>>>(z, sp_w1, sp_b1, sp_w2, sp_b2,
                                        out_npred, out_mask, out_batch);

    cudaFuncSetAttribute(dec_kernel, cudaFuncAttributeMaxDynamicSharedMemorySize,
                         DEC_SMEM_BYTES);
    int gridB = (B * MAXN) / BM;  // 8192
    dec_kernel<<<gridB, DEC_THREADS, DEC_SMEM_BYTES>>>(
        z, dec_w1, dec_b1, dec_w2, dec_b2, out_x);
}

// round 3
// speedup vs baseline: 2.2522x; 2.2522x over previous
#include <cuda_runtime.h>
#include <math.h>
#include <stdint.h>

#define MAXN 16
#define HDIM 64
#define DDIM 64
#define HID 40
#define BMAX 65536

#define LDA 68   // A/H tile row pitch (floats): conflict-free A-fragment loads
#define LDW 72   // weight tile row pitch (floats): conflict-free B-fragment loads

// ---------------- device scratch (no allocations allowed) ----------------
__device__ float g_pe[MAXN * HDIM];        // positional codes [16][64] fp32
__device__ int   g_n[BMAX];                // per-row argmax
__device__ uint32_t g_w1p[64 * LDW];       // W1 [k][n] tf32 bits, padded
__device__ uint32_t g_w2p[64 * LDW];       // W2 [k][n] tf32 bits, padded

// ---------------- helpers ----------------
__device__ __forceinline__ float gelu_tanh(float x) {
    float x3 = x * x * x;
    float t = tanhf(0.7978845608028654f * (x + 0.044715f * x3));
    return 0.5f * x * (1.0f + t);
}
// sigmoid form of tanh-gelu (mathematically identical), MUFU-based
__device__ __forceinline__ float gelu_fast(float x) {
    float u = x * (1.5957691216057308f + 0.07135481627f * x * x);
    float e = __expf(-u);
    return __fdividef(x, 1.0f + e);
}
__device__ __forceinline__ uint32_t tf32_bits(float x) {
    uint32_t r;
    asm("cvt.rn.tf32.f32 %0, %1;" : "=r"(r) : "f"(x));
    return r;
}

__device__ __forceinline__ void mma_tf32(float& c0, float& c1, float& c2, float& c3,
                                         uint32_t a0, uint32_t a1, uint32_t a2, uint32_t a3,
                                         uint32_t b0, uint32_t b1) {
    asm volatile(
        "mma.sync.aligned.m16n8k8.row.col.f32.tf32.tf32.f32 "
        "{%0,%1,%2,%3}, {%4,%5,%6,%7}, {%8,%9}, {%0,%1,%2,%3};"
        : "+f"(c0), "+f"(c1), "+f"(c2), "+f"(c3)
        : "r"(a0), "r"(a1), "r"(a2), "r"(a3), "r"(b0), "r"(b1));
}

// ================= prep: pe = MLP(eye(16)); tf32 weights [k][n] padded =================
__global__ void prep_kernel(const float* __restrict__ w1, const float* __restrict__ b1,
                            const float* __restrict__ w2, const float* __restrict__ b2,
                            const float* __restrict__ dw1, const float* __restrict__ dw2) {
    __shared__ float h[MAXN * HID];
    int tid = threadIdx.x;
    for (int i = tid; i < MAXN * HID; i += blockDim.x) {
        int j = i % HID;
        h[i] = gelu_tanh(w1[i] + b1[j]);
    }
    __syncthreads();
    for (int i = tid; i < MAXN * HDIM; i += blockDim.x) {
        int p = i / HDIM, d = i % HDIM;
        float acc = b2[d];
        #pragma unroll
        for (int j = 0; j < HID; j++) acc += h[p * HID + j] * w2[j * HDIM + d];
        g_pe[i] = acc;
    }
    // tf32-round decoder weights into padded [k][n] layout (k = row, as stored)
    for (int i = tid; i < 64 * 64; i += blockDim.x) {
        int k = i >> 6, n = i & 63;
        g_w1p[k * LDW + n] = tf32_bits(dw1[i]);
        g_w2p[k * LDW + n] = tf32_bits(dw2[i]);
    }
}

// ================= sp: size MLP + argmax + mask/batch/n_pred (exact fp32) =================
#define SP_ROWS 128
__global__ void __launch_bounds__(SP_ROWS) sp_kernel(
    const float* __restrict__ z,
    const float* __restrict__ w1, const float* __restrict__ b1,
    const float* __restrict__ w2, const float* __restrict__ b2,
    float* __restrict__ out_npred, float* __restrict__ out_mask,
    float* __restrict__ out_batch) {
    __shared__ float zs[SP_ROWS][68];
    __shared__ float w1s[HDIM * HID];
    __shared__ float w2s[HID * MAXN];
    __shared__ float b1s[HID];
    __shared__ float b2s[MAXN];

    int tid = threadIdx.x;
    int row0 = blockIdx.x * SP_ROWS;

    for (int i = tid; i < HDIM * HID; i += SP_ROWS) w1s[i] = w1[i];
    for (int i = tid; i < HID * MAXN; i += SP_ROWS) w2s[i] = w2[i];
    if (tid < HID)  b1s[tid] = b1[tid];
    if (tid < MAXN) b2s[tid] = b2[tid];
    for (int i = tid; i < SP_ROWS * (HDIM / 4); i += SP_ROWS) {
        int r = i / (HDIM / 4), c4 = i % (HDIM / 4);
        float4 v = ((const float4*)(z + (size_t)(row0 + r) * HDIM))[c4];
        *(float4*)&zs[r][c4 * 4] = v;
    }
    __syncthreads();

    int b = row0 + tid;
    float h[HID];
    #pragma unroll
    for (int j4 = 0; j4 < HID / 4; j4++) {
        float4 bv = *(const float4*)&b1s[j4 * 4];
        h[j4 * 4 + 0] = bv.x; h[j4 * 4 + 1] = bv.y;
        h[j4 * 4 + 2] = bv.z; h[j4 * 4 + 3] = bv.w;
    }
    for (int k = 0; k < HDIM; k++) {
        float zk = zs[tid][k];
        const float4* wr = (const float4*)&w1s[k * HID];
        #pragma unroll
        for (int j4 = 0; j4 < HID / 4; j4++) {
            float4 w = wr[j4];
            h[j4 * 4 + 0] += zk * w.x;
            h[j4 * 4 + 1] += zk * w.y;
            h[j4 * 4 + 2] += zk * w.z;
            h[j4 * 4 + 3] += zk * w.w;
        }
    }
    float o[MAXN];
    #pragma unroll
    for (int p4 = 0; p4 < MAXN / 4; p4++) {
        float4 bv = *(const float4*)&b2s[p4 * 4];
        o[p4 * 4 + 0] = bv.x; o[p4 * 4 + 1] = bv.y;
        o[p4 * 4 + 2] = bv.z; o[p4 * 4 + 3] = bv.w;
    }
    #pragma unroll
    for (int j = 0; j < HID; j++) {
        float hj = gelu_tanh(h[j]);
        const float4* wr = (const float4*)&w2s[j * MAXN];
        #pragma unroll
        for (int p4 = 0; p4 < MAXN / 4; p4++) {
            float4 w = wr[p4];
            o[p4 * 4 + 0] += hj * w.x;
            o[p4 * 4 + 1] += hj * w.y;
            o[p4 * 4 + 2] += hj * w.z;
            o[p4 * 4 + 3] += hj * w.w;
        }
    }
    int n = 0; float best = o[0];
    #pragma unroll
    for (int p = 1; p < MAXN; p++)
        if (o[p] > best) { best = o[p]; n = p; }
    g_n[b] = n;

    size_t base = (size_t)b * MAXN;
    #pragma unroll
    for (int p4 = 0; p4 < MAXN / 4; p4++)
        *(float4*)(out_npred + base + p4 * 4) =
            make_float4(o[p4 * 4 + 0], o[p4 * 4 + 1], o[p4 * 4 + 2], o[p4 * 4 + 3]);
    float fb = (float)b;
    #pragma unroll
    for (int p4 = 0; p4 < MAXN / 4; p4++) {
        float4 mv;
        mv.x = (p4 * 4 + 0 < n) ? 1.0f : 0.0f;
        mv.y = (p4 * 4 + 1 < n) ? 1.0f : 0.0f;
        mv.z = (p4 * 4 + 2 < n) ? 1.0f : 0.0f;
        mv.w = (p4 * 4 + 3 < n) ? 1.0f : 0.0f;
        *(float4*)(out_mask + base + p4 * 4) = mv;
        *(float4*)(out_batch + base + p4 * 4) = make_float4(fb, fb, fb, fb);
    }
}

// ================= dec: fused 2-layer MLP via mma.sync tf32 =================
#define DEC_THREADS 128
// smem layout (float indices)
#define SOFF_W1  0                       // 64*72 = 4608
#define SOFF_W2  (SOFF_W1 + 64 * LDW)    // 4608
#define SOFF_A   (SOFF_W2 + 64 * LDW)    // 128*68 = 8704 (A, reused as H)
#define SOFF_Z   (SOFF_A + 128 * LDA)    // 512
#define SOFF_PE  (SOFF_Z + 8 * 64)       // 1024
#define SOFF_B1  (SOFF_PE + MAXN * 64)   // 64
#define SOFF_B2  (SOFF_B1 + 64)          // 64
#define SOFF_NS  (SOFF_B2 + 64)          // 8
#define DEC_SMEM_FLOATS (SOFF_NS + 8)
#define DEC_SMEM_BYTES  (DEC_SMEM_FLOATS * 4)

__global__ void __launch_bounds__(DEC_THREADS) dec_kernel(
    const float* __restrict__ z,
    const float* __restrict__ b1, const float* __restrict__ b2,
    float* __restrict__ out_x) {
    extern __shared__ __align__(16) float smem[];
    uint32_t* W1s = (uint32_t*)(smem + SOFF_W1);
    uint32_t* W2s = (uint32_t*)(smem + SOFF_W2);
    uint32_t* As  = (uint32_t*)(smem + SOFF_A);
    float* zs  = smem + SOFF_Z;
    float* pes = smem + SOFF_PE;
    float* b1s = smem + SOFF_B1;
    float* b2s = smem + SOFF_B2;
    int*   ns  = (int*)(smem + SOFF_NS);

    int tid = threadIdx.x;
    int wid = tid >> 5;
    int lane = tid & 31;
    int m_base = blockIdx.x * 128;
    int zrow0 = m_base >> 4;             // 8 consecutive z rows

    // ---- prologue loads ----
    {
        const uint4* w1g = (const uint4*)g_w1p;
        const uint4* w2g = (const uint4*)g_w2p;
        uint4* w1d = (uint4*)W1s;
        uint4* w2d = (uint4*)W2s;
        #pragma unroll
        for (int i = 0; i < 9; i++) {
            w1d[tid + i * DEC_THREADS] = w1g[tid + i * DEC_THREADS];
            w2d[tid + i * DEC_THREADS] = w2g[tid + i * DEC_THREADS];
        }
        for (int i = tid; i < 8 * 64 / 4; i += DEC_THREADS)
            ((float4*)zs)[i] = ((const float4*)(z + (size_t)zrow0 * HDIM))[i];
        for (int i = tid; i < MAXN * 64 / 4; i += DEC_THREADS)
            ((float4*)pes)[i] = ((const float4*)g_pe)[i];
        if (tid < 64) { b1s[tid] = b1[tid]; b2s[tid] = b2[tid]; }
        if (tid < 8) ns[tid] = g_n[zrow0 + tid];
    }
    __syncthreads();

    // ---- build A = zp tile (tf32 bits) ----
    #pragma unroll
    for (int it = 0; it < 16; it++) {
        int i = tid + it * DEC_THREADS;      // (m, k4) over 128 x 16
        int m = i >> 4;
        int k = (i & 15) << 2;
        int zr = m >> 4, p = m & 15;
        float4 zv = *(const float4*)&zs[zr * 64 + k];
        float4 pv = *(const float4*)&pes[p * 64 + k];
        uint4 o;
        o.x = tf32_bits(zv.x * pv.x);
        o.y = tf32_bits(zv.y * pv.y);
        o.z = tf32_bits(zv.z * pv.z);
        o.w = tf32_bits(zv.w * pv.w);
        *(uint4*)&As[m * LDA + k] = o;
    }
    __syncthreads();

    int m0 = wid * 32;                   // this warp owns rows [m0, m0+32)
    int grp = lane >> 2;                 // 0..7
    int rem = lane & 3;                  // 0..3

    float C[2][8][4];

    // ================= GEMM1: H = gelu(A @ W1 + b1) =================
    #pragma unroll
    for (int mt = 0; mt < 2; mt++)
        #pragma unroll
        for (int nt = 0; nt < 8; nt++)
            #pragma unroll
            for (int q = 0; q < 4; q++) C[mt][nt][q] = 0.0f;

    #pragma unroll
    for (int k0 = 0; k0 < 64; k0 += 8) {
        uint32_t bf0[8], bf1[8];
        int brow = k0 + rem;
        #pragma unroll
        for (int nt = 0; nt < 8; nt++) {
            bf0[nt] = W1s[brow * LDW + nt * 8 + grp];
            bf1[nt] = W1s[(brow + 4) * LDW + nt * 8 + grp];
        }
        #pragma unroll
        for (int mt = 0; mt < 2; mt++) {
            int ar = m0 + mt * 16 + grp;
            int ac = k0 + rem;
            uint32_t a0 = As[ar * LDA + ac];
            uint32_t a1 = As[(ar + 8) * LDA + ac];
            uint32_t a2 = As[ar * LDA + ac + 4];
            uint32_t a3 = As[(ar + 8) * LDA + ac + 4];
            #pragma unroll
            for (int nt = 0; nt < 8; nt++)
                mma_tf32(C[mt][nt][0], C[mt][nt][1], C[mt][nt][2], C[mt][nt][3],
                         a0, a1, a2, a3, bf0[nt], bf1[nt]);
        }
    }

    // epilogue1: bias + gelu -> tf32, store into A region (own rows only)
    #pragma unroll
    for (int mt = 0; mt < 2; mt++) {
        int r0 = m0 + mt * 16 + grp;
        #pragma unroll
        for (int nt = 0; nt < 8; nt++) {
            int col = nt * 8 + 2 * rem;
            float bx = b1s[col], by = b1s[col + 1];
            uint2 lo, hi;
            lo.x = tf32_bits(gelu_fast(C[mt][nt][0] + bx));
            lo.y = tf32_bits(gelu_fast(C[mt][nt][1] + by));
            hi.x = tf32_bits(gelu_fast(C[mt][nt][2] + bx));
            hi.y = tf32_bits(gelu_fast(C[mt][nt][3] + by));
            *(uint2*)&As[r0 * LDA + col] = lo;
            *(uint2*)&As[(r0 + 8) * LDA + col] = hi;
        }
    }
    __syncwarp();

    // ================= GEMM2: X = H @ W2 + b2 =================
    #pragma unroll
    for (int mt = 0; mt < 2; mt++)
        #pragma unroll
        for (int nt = 0; nt < 8; nt++)
            #pragma unroll
            for (int q = 0; q < 4; q++) C[mt][nt][q] = 0.0f;

    #pragma unroll
    for (int k0 = 0; k0 < 64; k0 += 8) {
        uint32_t bf0[8], bf1[8];
        int brow = k0 + rem;
        #pragma unroll
        for (int nt = 0; nt < 8; nt++) {
            bf0[nt] = W2s[brow * LDW + nt * 8 + grp];
            bf1[nt] = W2s[(brow + 4) * LDW + nt * 8 + grp];
        }
        #pragma unroll
        for (int mt = 0; mt < 2; mt++) {
            int ar = m0 + mt * 16 + grp;
            int ac = k0 + rem;
            uint32_t a0 = As[ar * LDA + ac];
            uint32_t a1 = As[(ar + 8) * LDA + ac];
            uint32_t a2 = As[ar * LDA + ac + 4];
            uint32_t a3 = As[(ar + 8) * LDA + ac + 4];
            #pragma unroll
            for (int nt = 0; nt < 8; nt++)
                mma_tf32(C[mt][nt][0], C[mt][nt][1], C[mt][nt][2], C[mt][nt][3],
                         a0, a1, a2, a3, bf0[nt], bf1[nt]);
        }
    }

    // epilogue2: bias + mask + store
    #pragma unroll
    for (int mt = 0; mt < 2; mt++) {
        int r0 = m0 + mt * 16 + grp;      // local row
        int r1 = r0 + 8;
        bool v0 = (r0 & 15) < ns[r0 >> 4];
        bool v1 = (r1 & 15) < ns[r1 >> 4];
        float* orow0 = out_x + (size_t)(m_base + r0) * DDIM;
        float* orow1 = out_x + (size_t)(m_base + r1) * DDIM;
        #pragma unroll
        for (int nt = 0; nt < 8; nt++) {
            int col = nt * 8 + 2 * rem;
            float bx = b2s[col], by = b2s[col + 1];
            float2 lo, hi;
            lo.x = v0 ? (C[mt][nt][0] + bx) : 0.0f;
            lo.y = v0 ? (C[mt][nt][1] + by) : 0.0f;
            hi.x = v1 ? (C[mt][nt][2] + bx) : 0.0f;
            hi.y = v1 ? (C[mt][nt][3] + by) : 0.0f;
            *(float2*)(orow0 + col) = lo;
            *(float2*)(orow1 + col) = hi;
        }
    }
}

// ================= launch =================
extern "C" void kernel_launch(void* const* d_in, const int* in_sizes, int n_in,
                              void* d_out, int out_size) {
    const float* z      = (const float*)d_in[0];
    const float* sp_w1  = (const float*)d_in[1];
    const float* sp_b1  = (const float*)d_in[2];
    const float* sp_w2  = (const float*)d_in[3];
    const float* sp_b2  = (const float*)d_in[4];
    const float* pe_w1  = (const float*)d_in[5];
    const float* pe_b1  = (const float*)d_in[6];
    const float* pe_w2  = (const float*)d_in[7];
    const float* pe_b2  = (const float*)d_in[8];
    const float* dec_w1 = (const float*)d_in[9];
    const float* dec_b1 = (const float*)d_in[10];
    const float* dec_w2 = (const float*)d_in[11];
    const float* dec_b2 = (const float*)d_in[12];

    int B = in_sizes[0] / HDIM;   // 65536

    float* out = (float*)d_out;
    float* out_x     = out;                               // [B,16,64]
    float* out_mask  = out_x + (size_t)B * MAXN * DDIM;   // [B,16]
    float* out_batch = out_mask + (size_t)B * MAXN;       // [B,16]
    float* out_npred = out_batch + (size_t)B * MAXN;      // [B,16]

    prep_kernel<<<1, 256>>>(pe_w1, pe_b1, pe_w2, pe_b2, dec_w1, dec_w2);
    sp_kernel<<<B / SP_ROWS, SP_ROWS>>>(z, sp_w1, sp_b1, sp_w2, sp_b2,
                                        out_npred, out_mask, out_batch);

    cudaFuncSetAttribute(dec_kernel, cudaFuncAttributeMaxDynamicSharedMemorySize,
                         DEC_SMEM_BYTES);
    int gridB = (B * MAXN) / 128;  // 8192
    dec_kernel<<<gridB, DEC_THREADS, DEC_SMEM_BYTES>>>(z, dec_b1, dec_b2, out_x);
}

// round 5
// speedup vs baseline: 2.6302x; 1.1678x over previous
#include <cuda_runtime.h>
#include <math.h>
#include <stdint.h>

#define MAXN 16
#define HDIM 64
#define DDIM 64
#define HID 40
#define BMAX 65536

// ---------------- device scratch (no allocations allowed) ----------------
__device__ float g_pe[MAXN * HDIM];        // positional codes [16][64] fp32
__device__ int   g_n[BMAX];                // per-row argmax

// ---------------- helpers ----------------
__device__ __forceinline__ float gelu_tanh(float x) {
    float x3 = x * x * x;
    float t = tanhf(0.7978845608028654f * (x + 0.044715f * x3));
    return 0.5f * x * (1.0f + t);
}
// sigmoid form of tanh-gelu (mathematically identical), MUFU-based
__device__ __forceinline__ float gelu_fast(float x) {
    float u = x * (1.5957691216057308f + 0.07135481627f * x * x);
    float e = __expf(-u);
    return __fdividef(x, 1.0f + e);
}
__device__ __forceinline__ uint32_t tf32_bits(float x) {
    uint32_t r;
    asm("cvt.rn.tf32.f32 %0, %1;" : "=r"(r) : "f"(x));
    return r;
}
__device__ __forceinline__ void mma_tf32(float& c0, float& c1, float& c2, float& c3,
                                         uint32_t a0, uint32_t a1, uint32_t a2, uint32_t a3,
                                         uint32_t b0, uint32_t b1) {
    asm volatile(
        "mma.sync.aligned.m16n8k8.row.col.f32.tf32.tf32.f32 "
        "{%0,%1,%2,%3}, {%4,%5,%6,%7}, {%8,%9}, {%0,%1,%2,%3};"
        : "+f"(c0), "+f"(c1), "+f"(c2), "+f"(c3)
        : "r"(a0), "r"(a1), "r"(a2), "r"(a3), "r"(b0), "r"(b1));
}

// ================= prep: pe = MLP(eye(16)) only =================
__global__ void prep_kernel(const float* __restrict__ w1, const float* __restrict__ b1,
                            const float* __restrict__ w2, const float* __restrict__ b2) {
    __shared__ float h[MAXN * HID];
    int tid = threadIdx.x;
    for (int i = tid; i < MAXN * HID; i += blockDim.x) {
        int j = i % HID;
        h[i] = gelu_tanh(w1[i] + b1[j]);
    }
    __syncthreads();
    for (int i = tid; i < MAXN * HDIM; i += blockDim.x) {
        int p = i >> 6, d = i & 63;
        float acc = b2[d];
        #pragma unroll
        for (int j = 0; j < HID; j++) acc += h[p * HID + j] * w2[j * HDIM + d];
        g_pe[i] = acc;
    }
}

// ================= sp: size MLP + argmax + mask/batch/n_pred (exact fp32) =================
#define SP_ROWS 128
__global__ void __launch_bounds__(SP_ROWS) sp_kernel(
    const float* __restrict__ z,
    const float* __restrict__ w1, const float* __restrict__ b1,
    const float* __restrict__ w2, const float* __restrict__ b2,
    float* __restrict__ out_npred, float* __restrict__ out_mask,
    float* __restrict__ out_batch) {
    __shared__ float zs[SP_ROWS][65];     // pitch 65: conflict-free zs[tid][k] reads
    __shared__ float w1s[HDIM * HID];
    __shared__ float w2s[HID * MAXN];
    __shared__ float b1s[HID];
    __shared__ float b2s[MAXN];

    int tid = threadIdx.x;
    int row0 = blockIdx.x * SP_ROWS;

    for (int i = tid; i < HDIM * HID; i += SP_ROWS) w1s[i] = w1[i];
    for (int i = tid; i < HID * MAXN; i += SP_ROWS) w2s[i] = w2[i];
    if (tid < HID)  b1s[tid] = b1[tid];
    if (tid < MAXN) b2s[tid] = b2[tid];
    for (int i = tid; i < SP_ROWS * (HDIM / 4); i += SP_ROWS) {
        int r = i / (HDIM / 4), c4 = i % (HDIM / 4);
        float4 v = ((const float4*)(z + (size_t)(row0 + r) * HDIM))[c4];
        zs[r][c4 * 4 + 0] = v.x;
        zs[r][c4 * 4 + 1] = v.y;
        zs[r][c4 * 4 + 2] = v.z;
        zs[r][c4 * 4 + 3] = v.w;
    }
    __syncthreads();

    int b = row0 + tid;
    float h[HID];
    #pragma unroll
    for (int j4 = 0; j4 < HID / 4; j4++) {
        float4 bv = *(const float4*)&b1s[j4 * 4];
        h[j4 * 4 + 0] = bv.x; h[j4 * 4 + 1] = bv.y;
        h[j4 * 4 + 2] = bv.z; h[j4 * 4 + 3] = bv.w;
    }
    for (int k = 0; k < HDIM; k++) {
        float zk = zs[tid][k];
        const float4* wr = (const float4*)&w1s[k * HID];
        #pragma unroll
        for (int j4 = 0; j4 < HID / 4; j4++) {
            float4 w = wr[j4];
            h[j4 * 4 + 0] += zk * w.x;
            h[j4 * 4 + 1] += zk * w.y;
            h[j4 * 4 + 2] += zk * w.z;
            h[j4 * 4 + 3] += zk * w.w;
        }
    }
    float o[MAXN];
    #pragma unroll
    for (int p4 = 0; p4 < MAXN / 4; p4++) {
        float4 bv = *(const float4*)&b2s[p4 * 4];
        o[p4 * 4 + 0] = bv.x; o[p4 * 4 + 1] = bv.y;
        o[p4 * 4 + 2] = bv.z; o[p4 * 4 + 3] = bv.w;
    }
    #pragma unroll
    for (int j = 0; j < HID; j++) {
        float hj = gelu_tanh(h[j]);
        const float4* wr = (const float4*)&w2s[j * MAXN];
        #pragma unroll
        for (int p4 = 0; p4 < MAXN / 4; p4++) {
            float4 w = wr[p4];
            o[p4 * 4 + 0] += hj * w.x;
            o[p4 * 4 + 1] += hj * w.y;
            o[p4 * 4 + 2] += hj * w.z;
            o[p4 * 4 + 3] += hj * w.w;
        }
    }
    int n = 0; float best = o[0];
    #pragma unroll
    for (int p = 1; p < MAXN; p++)
        if (o[p] > best) { best = o[p]; n = p; }
    g_n[b] = n;

    size_t base = (size_t)b * MAXN;
    #pragma unroll
    for (int p4 = 0; p4 < MAXN / 4; p4++)
        *(float4*)(out_npred + base + p4 * 4) =
            make_float4(o[p4 * 4 + 0], o[p4 * 4 + 1], o[p4 * 4 + 2], o[p4 * 4 + 3]);
    float fb = (float)b;
    #pragma unroll
    for (int p4 = 0; p4 < MAXN / 4; p4++) {
        float4 mv;
        mv.x = (p4 * 4 + 0 < n) ? 1.0f : 0.0f;
        mv.y = (p4 * 4 + 1 < n) ? 1.0f : 0.0f;
        mv.z = (p4 * 4 + 2 < n) ? 1.0f : 0.0f;
        mv.w = (p4 * 4 + 3 < n) ? 1.0f : 0.0f;
        *(float4*)(out_mask + base + p4 * 4) = mv;
        *(float4*)(out_batch + base + p4 * 4) = make_float4(fb, fb, fb, fb);
    }
}

// ================= dec: persistent, warp-independent strips =================
#define DEC_THREADS 256
#define DLDA 68   // A/H strip pitch
#define DLDW 72   // weight pitch
// smem layout (float indices)
#define SOFF_W1 0                          // 64*72 = 4608
#define SOFF_W2 (SOFF_W1 + 64 * DLDW)      // 4608
#define SOFF_A  (SOFF_W2 + 64 * DLDW)      // 8 warps * 32*68 = 17408
#define SOFF_PE (SOFF_A + 8 * 32 * DLDA)   // 1024
#define SOFF_ZB (SOFF_PE + MAXN * 64)      // 8 warps * 128 = 1024
#define SOFF_B1 (SOFF_ZB + 8 * 128)        // 64
#define SOFF_B2 (SOFF_B1 + 64)             // 64
#define DEC_SMEM_FLOATS (SOFF_B2 + 64)
#define DEC_SMEM_BYTES  (DEC_SMEM_FLOATS * 4)

__global__ void __launch_bounds__(DEC_THREADS) dec_kernel(
    const float* __restrict__ z,
    const float* __restrict__ dw1, const float* __restrict__ db1,
    const float* __restrict__ dw2, const float* __restrict__ db2,
    float* __restrict__ out_x, int nstrips) {
    extern __shared__ __align__(16) float smem[];
    uint32_t* W1s = (uint32_t*)(smem + SOFF_W1);
    uint32_t* W2s = (uint32_t*)(smem + SOFF_W2);
    float* pes = smem + SOFF_PE;
    float* b1s = smem + SOFF_B1;
    float* b2s = smem + SOFF_B2;

    int tid = threadIdx.x;
    int wid = tid >> 5;
    int lane = tid & 31;
    int grp = lane >> 2;                   // 0..7
    int rem = lane & 3;                    // 0..3

    // ---- one-time prologue: convert weights to tf32, stage pe/biases ----
    for (int i = tid; i < 64 * 64; i += DEC_THREADS) {
        int k = i >> 6, n = i & 63;
        W1s[k * DLDW + n] = tf32_bits(dw1[i]);
        W2s[k * DLDW + n] = tf32_bits(dw2[i]);
    }
    for (int i = tid; i < MAXN * 64 / 4; i += DEC_THREADS)
        ((float4*)pes)[i] = ((const float4*)g_pe)[i];
    if (tid < 64) { b1s[tid] = b1s[tid] = db1[tid]; b2s[tid] = db2[tid]; }
    __syncthreads();

    uint32_t* Aw = (uint32_t*)(smem + SOFF_A) + wid * 32 * DLDA;
    float* zw = smem + SOFF_ZB + wid * 128;

    int stride = gridDim.x * 8;
    int s = blockIdx.x * 8 + wid;
    if (s >= nstrips) return;

    // first strip's z
    float4 zcur = ((const float4*)(z + (size_t)s * 128))[lane];

    for (; s < nstrips; s += stride) {
        *(float4*)&zw[lane * 4] = zcur;
        int n0 = g_n[s * 2 + 0];
        int n1 = g_n[s * 2 + 1];
        __syncwarp();

        // ---- build A strip (32 x 64, tf32) ----
        #pragma unroll
        for (int it = 0; it < 16; it++) {
            int i = lane + it * 32;
            int m = i >> 4;              // 0..31
            int k = (i & 15) << 2;
            int zr = m >> 4, p = m & 15;
            float4 zv = *(const float4*)&zw[zr * 64 + k];
            float4 pv = *(const float4*)&pes[p * 64 + k];
            uint4 o;
            o.x = tf32_bits(zv.x * pv.x);
            o.y = tf32_bits(zv.y * pv.y);
            o.z = tf32_bits(zv.z * pv.z);
            o.w = tf32_bits(zv.w * pv.w);
            *(uint4*)&Aw[m * DLDA + k] = o;
        }
        __syncwarp();

        // prefetch next strip's z (hides DRAM latency behind the GEMMs)
        int snext = s + stride;
        if (snext < nstrips)
            zcur = ((const float4*)(z + (size_t)snext * 128))[lane];

        float C[2][8][4];

        // ---- GEMM1: H = gelu(A @ W1 + b1) ----
        #pragma unroll
        for (int mt = 0; mt < 2; mt++)
            #pragma unroll
            for (int nt = 0; nt < 8; nt++)
                #pragma unroll
                for (int q = 0; q < 4; q++) C[mt][nt][q] = 0.0f;

        #pragma unroll
        for (int k0 = 0; k0 < 64; k0 += 8) {
            uint32_t bf0[8], bf1[8];
            int brow = k0 + rem;
            #pragma unroll
            for (int nt = 0; nt < 8; nt++) {
                bf0[nt] = W1s[brow * DLDW + nt * 8 + grp];
                bf1[nt] = W1s[(brow + 4) * DLDW + nt * 8 + grp];
            }
            #pragma unroll
            for (int mt = 0; mt < 2; mt++) {
                int ar = mt * 16 + grp;
                int ac = k0 + rem;
                uint32_t a0 = Aw[ar * DLDA + ac];
                uint32_t a1 = Aw[(ar + 8) * DLDA + ac];
                uint32_t a2 = Aw[ar * DLDA + ac + 4];
                uint32_t a3 = Aw[(ar + 8) * DLDA + ac + 4];
                #pragma unroll
                for (int nt = 0; nt < 8; nt++)
                    mma_tf32(C[mt][nt][0], C[mt][nt][1], C[mt][nt][2], C[mt][nt][3],
                             a0, a1, a2, a3, bf0[nt], bf1[nt]);
            }
        }
        __syncwarp();

        // ---- epilogue1: bias + gelu -> tf32, in-place H ----
        #pragma unroll
        for (int mt = 0; mt < 2; mt++) {
            int r0 = mt * 16 + grp;
            #pragma unroll
            for (int nt = 0; nt < 8; nt++) {
                int col = nt * 8 + 2 * rem;
                float bx = b1s[col], by = b1s[col + 1];
                uint2 lo, hi;
                lo.x = tf32_bits(gelu_fast(C[mt][nt][0] + bx));
                lo.y = tf32_bits(gelu_fast(C[mt][nt][1] + by));
                hi.x = tf32_bits(gelu_fast(C[mt][nt][2] + bx));
                hi.y = tf32_bits(gelu_fast(C[mt][nt][3] + by));
                *(uint2*)&Aw[r0 * DLDA + col] = lo;
                *(uint2*)&Aw[(r0 + 8) * DLDA + col] = hi;
            }
        }
        __syncwarp();

        // ---- GEMM2: X = H @ W2 + b2 ----
        #pragma unroll
        for (int mt = 0; mt < 2; mt++)
            #pragma unroll
            for (int nt = 0; nt < 8; nt++)
                #pragma unroll
                for (int q = 0; q < 4; q++) C[mt][nt][q] = 0.0f;

        #pragma unroll
        for (int k0 = 0; k0 < 64; k0 += 8) {
            uint32_t bf0[8], bf1[8];
            int brow = k0 + rem;
            #pragma unroll
            for (int nt = 0; nt < 8; nt++) {
                bf0[nt] = W2s[brow * DLDW + nt * 8 + grp];
                bf1[nt] = W2s[(brow + 4) * DLDW + nt * 8 + grp];
            }
            #pragma unroll
            for (int mt = 0; mt < 2; mt++) {
                int ar = mt * 16 + grp;
                int ac = k0 + rem;
                uint32_t a0 = Aw[ar * DLDA + ac];
                uint32_t a1 = Aw[(ar + 8) * DLDA + ac];
                uint32_t a2 = Aw[ar * DLDA + ac + 4];
                uint32_t a3 = Aw[(ar + 8) * DLDA + ac + 4];
                #pragma unroll
                for (int nt = 0; nt < 8; nt++)
                    mma_tf32(C[mt][nt][0], C[mt][nt][1], C[mt][nt][2], C[mt][nt][3],
                             a0, a1, a2, a3, bf0[nt], bf1[nt]);
            }
        }

        // ---- epilogue2: bias + mask + store ----
        #pragma unroll
        for (int mt = 0; mt < 2; mt++) {
            int nm = mt ? n1 : n0;
            bool v0 = grp < nm;
            bool v1 = grp + 8 < nm;
            int r0 = mt * 16 + grp;
            float* orow0 = out_x + ((size_t)s * 32 + r0) * DDIM;
            float* orow1 = orow0 + 8 * DDIM;
            #pragma unroll
            for (int nt = 0; nt < 8; nt++) {
                int col = nt * 8 + 2 * rem;
                float bx = b2s[col], by = b2s[col + 1];
                float2 lo, hi;
                lo.x = v0 ? (C[mt][nt][0] + bx) : 0.0f;
                lo.y = v0 ? (C[mt][nt][1] + by) : 0.0f;
                hi.x = v1 ? (C[mt][nt][2] + bx) : 0.0f;
                hi.y = v1 ? (C[mt][nt][3] + by) : 0.0f;
                *(float2*)(orow0 + col) = lo;
                *(float2*)(orow1 + col) = hi;
            }
        }
        __syncwarp();
    }
}

// ================= launch =================
extern "C" void kernel_launch(void* const* d_in, const int* in_sizes, int n_in,
                              void* d_out, int out_size) {
    const float* z      = (const float*)d_in[0];
    const float* sp_w1  = (const float*)d_in[1];
    const float* sp_b1  = (const float*)d_in[2];
    const float* sp_w2  = (const float*)d_in[3];
    const float* sp_b2  = (const float*)d_in[4];
    const float* pe_w1  = (const float*)d_in[5];
    const float* pe_b1  = (const float*)d_in[6];
    const float* pe_w2  = (const float*)d_in[7];
    const float* pe_b2  = (const float*)d_in[8];
    const float* dec_w1 = (const float*)d_in[9];
    const float* dec_b1 = (const float*)d_in[10];
    const float* dec_w2 = (const float*)d_in[11];
    const float* dec_b2 = (const float*)d_in[12];

    int B = in_sizes[0] / HDIM;   // 65536

    float* out = (float*)d_out;
    float* out_x     = out;                               // [B,16,64]
    float* out_mask  = out_x + (size_t)B * MAXN * DDIM;   // [B,16]
    float* out_batch = out_mask + (size_t)B * MAXN;       // [B,16]
    float* out_npred = out_batch + (size_t)B * MAXN;      // [B,16]

    static int nsm = 0;
    if (!nsm) {
        cudaDeviceGetAttribute(&nsm, cudaDevAttrMultiProcessorCount, 0);
        if (nsm <= 0) nsm = 148;
        cudaFuncSetAttribute(dec_kernel, cudaFuncAttributeMaxDynamicSharedMemorySize,
                             DEC_SMEM_BYTES);
    }

    prep_kernel<<<1, 256>>>(pe_w1, pe_b1, pe_w2, pe_b2);
    sp_kernel<<<B / SP_ROWS, SP_ROWS>>>(z, sp_w1, sp_b1, sp_w2, sp_b2,
                                        out_npred, out_mask, out_batch);

    int nstrips = B / 2;   // 32768 strips of 32 rows
    dec_kernel<<<nsm, DEC_THREADS, DEC_SMEM_BYTES>>>(
        z, dec_w1, dec_b1, dec_w2, dec_b2, out_x, nstrips);
}

// round 8
// speedup vs baseline: 3.9829x; 1.5143x over previous
#include <cuda_runtime.h>
#include <cuda_fp16.h>
#include <math.h>
#include <stdint.h>

#define MAXN 16
#define HDIM 64
#define DDIM 64
#define HID 40
#define BMAX 65536

// ---------------- device scratch (no allocations allowed) ----------------
__device__ int g_n[BMAX];                  // per-row argmax

// ---------------- helpers ----------------
__device__ __forceinline__ float gelu_tanh(float x) {
    float x3 = x * x * x;
    float t = tanhf(0.7978845608028654f * (x + 0.044715f * x3));
    return 0.5f * x * (1.0f + t);
}
// sigmoid form of tanh-gelu (mathematically identical), MUFU-based
__device__ __forceinline__ float gelu_fast(float x) {
    float u = x * (1.5957691216057308f + 0.07135481627f * x * x);
    float e = __expf(-u);
    return __fdividef(x, 1.0f + e);
}
// pack two floats -> half2 bits (lo in low 16 bits)
__device__ __forceinline__ uint32_t f2h2(float lo, float hi) {
    uint32_t r;
    asm("cvt.rn.f16x2.f32 %0, %1, %2;" : "=r"(r) : "f"(hi), "f"(lo));
    return r;
}
__device__ __forceinline__ void mma_f16(float& c0, float& c1, float& c2, float& c3,
                                        uint32_t a0, uint32_t a1, uint32_t a2, uint32_t a3,
                                        uint32_t b0, uint32_t b1) {
    asm volatile(
        "mma.sync.aligned.m16n8k16.row.col.f32.f16.f16.f32 "
        "{%0,%1,%2,%3}, {%4,%5,%6,%7}, {%8,%9}, {%0,%1,%2,%3};"
        : "+f"(c0), "+f"(c1), "+f"(c2), "+f"(c3)
        : "r"(a0), "r"(a1), "r"(a2), "r"(a3), "r"(b0), "r"(b1));
}

// ================= sp: size MLP + argmax + mask/batch/n_pred (exact fp32) =================
#define SP_ROWS 128
__global__ void __launch_bounds__(SP_ROWS) sp_kernel(
    const float* __restrict__ z,
    const float* __restrict__ w1, const float* __restrict__ b1,
    const float* __restrict__ w2, const float* __restrict__ b2,
    float* __restrict__ out_npred, float* __restrict__ out_mask,
    float* __restrict__ out_batch) {
    __shared__ float zs[SP_ROWS][65];     // pitch 65: conflict-free zs[tid][k]
    __shared__ float w1s[HDIM * HID];
    __shared__ float w2s[HID * MAXN];
    __shared__ float b1s[HID];
    __shared__ float b2s[MAXN];

    int tid = threadIdx.x;
    int row0 = blockIdx.x * SP_ROWS;

    for (int i = tid; i < HDIM * HID; i += SP_ROWS) w1s[i] = w1[i];
    for (int i = tid; i < HID * MAXN; i += SP_ROWS) w2s[i] = w2[i];
    if (tid < HID)  b1s[tid] = b1[tid];
    if (tid < MAXN) b2s[tid] = b2[tid];
    for (int i = tid; i < SP_ROWS * (HDIM / 4); i += SP_ROWS) {
        int r = i / (HDIM / 4), c4 = i % (HDIM / 4);
        float4 v = ((const float4*)(z + (size_t)(row0 + r) * HDIM))[c4];
        zs[r][c4 * 4 + 0] = v.x;
        zs[r][c4 * 4 + 1] = v.y;
        zs[r][c4 * 4 + 2] = v.z;
        zs[r][c4 * 4 + 3] = v.w;
    }
    __syncthreads();

    int b = row0 + tid;
    float h[HID];
    #pragma unroll
    for (int j4 = 0; j4 < HID / 4; j4++) {
        float4 bv = *(const float4*)&b1s[j4 * 4];
        h[j4 * 4 + 0] = bv.x; h[j4 * 4 + 1] = bv.y;
        h[j4 * 4 + 2] = bv.z; h[j4 * 4 + 3] = bv.w;
    }
    for (int k = 0; k < HDIM; k++) {
        float zk = zs[tid][k];
        const float4* wr = (const float4*)&w1s[k * HID];
        #pragma unroll
        for (int j4 = 0; j4 < HID / 4; j4++) {
            float4 w = wr[j4];
            h[j4 * 4 + 0] += zk * w.x;
            h[j4 * 4 + 1] += zk * w.y;
            h[j4 * 4 + 2] += zk * w.z;
            h[j4 * 4 + 3] += zk * w.w;
        }
    }
    float o[MAXN];
    #pragma unroll
    for (int p4 = 0; p4 < MAXN / 4; p4++) {
        float4 bv = *(const float4*)&b2s[p4 * 4];
        o[p4 * 4 + 0] = bv.x; o[p4 * 4 + 1] = bv.y;
        o[p4 * 4 + 2] = bv.z; o[p4 * 4 + 3] = bv.w;
    }
    #pragma unroll
    for (int j = 0; j < HID; j++) {
        float hj = gelu_tanh(h[j]);
        const float4* wr = (const float4*)&w2s[j * MAXN];
        #pragma unroll
        for (int p4 = 0; p4 < MAXN / 4; p4++) {
            float4 w = wr[p4];
            o[p4 * 4 + 0] += hj * w.x;
            o[p4 * 4 + 1] += hj * w.y;
            o[p4 * 4 + 2] += hj * w.z;
            o[p4 * 4 + 3] += hj * w.w;
        }
    }
    int n = 0; float best = o[0];
    #pragma unroll
    for (int p = 1; p < MAXN; p++)
        if (o[p] > best) { best = o[p]; n = p; }
    g_n[b] = n;

    size_t base = (size_t)b * MAXN;
    #pragma unroll
    for (int p4 = 0; p4 < MAXN / 4; p4++)
        *(float4*)(out_npred + base + p4 * 4) =
            make_float4(o[p4 * 4 + 0], o[p4 * 4 + 1], o[p4 * 4 + 2], o[p4 * 4 + 3]);
    float fb = (float)b;
    #pragma unroll
    for (int p4 = 0; p4 < MAXN / 4; p4++) {
        float4 mv;
        mv.x = (p4 * 4 + 0 < n) ? 1.0f : 0.0f;
        mv.y = (p4 * 4 + 1 < n) ? 1.0f : 0.0f;
        mv.z = (p4 * 4 + 2 < n) ? 1.0f : 0.0f;
        mv.w = (p4 * 4 + 3 < n) ? 1.0f : 0.0f;
        *(float4*)(out_mask + base + p4 * 4) = mv;
        *(float4*)(out_batch + base + p4 * 4) = make_float4(fb, fb, fb, fb);
    }
}

// ================= dec: persistent fp16-MMA fused MLP =================
#define DEC_THREADS 256
// dynamic smem layout (float indices)
#define SOFF_PE  0                      // 1024 floats: pe [16][64]
#define SOFF_HID (SOFF_PE + 1024)       // 640: pe-MLP hidden
#define SOFF_B1  (SOFF_HID + 640)       // 64
#define SOFF_B2  (SOFF_B1 + 64)         // 64
#define SOFF_ZB  (SOFF_B2 + 64)         // 8 warps * 128
#define SOFF_W2H (SOFF_ZB + 1024)       // 2304 u32: W2^T half [n][72]
#define SOFF_HH  (SOFF_W2H + 2304)      // 8 warps * 1152 u32: H half [32][72]
#define DEC_SMEM_FLOATS (SOFF_HH + 9216)
#define DEC_SMEM_BYTES  (DEC_SMEM_FLOATS * 4)

__global__ void __launch_bounds__(DEC_THREADS, 1) dec_kernel(
    const float* __restrict__ z,
    const float* __restrict__ dw1, const float* __restrict__ db1,
    const float* __restrict__ dw2, const float* __restrict__ db2,
    const float* __restrict__ pw1, const float* __restrict__ pb1,
    const float* __restrict__ pw2, const float* __restrict__ pb2,
    float* __restrict__ out_x, int nstrips) {
    extern __shared__ __align__(16) float smem[];
    float* pe_f = smem + SOFF_PE;
    float* hid  = smem + SOFF_HID;
    float* b1s  = smem + SOFF_B1;
    float* b2s  = smem + SOFF_B2;
    float* zb   = smem + SOFF_ZB;
    uint32_t* W2h = (uint32_t*)(smem + SOFF_W2H);
    uint32_t* Hh  = (uint32_t*)(smem + SOFF_HH);

    int tid = threadIdx.x;
    int wid = tid >> 5;
    int lane = tid & 31;
    int grp = lane >> 2;                 // 0..7
    int rem = lane & 3;                  // 0..3

    // ---- one-time prologue ----
    // pe hidden: gelu(pe_w1 + pe_b1) for one-hot input
    for (int i = tid; i < MAXN * HID; i += DEC_THREADS)
        hid[i] = gelu_tanh(pw1[i] + pb1[i % HID]);
    if (tid < 64) { b1s[tid] = db1[tid]; b2s[tid] = db2[tid]; }
    __syncthreads();
    // pe = hidden @ pe_w2 + pe_b2
    for (int i = tid; i < MAXN * 64; i += DEC_THREADS) {
        int p = i >> 6, d = i & 63;
        float acc = pb2[d];
        #pragma unroll
        for (int j = 0; j < HID; j++) acc += hid[p * HID + j] * pw2[j * 64 + d];
        pe_f[i] = acc;
    }
    // W2^T as half, n-major, pitch 72 halves
    for (int i = tid; i < 64 * 64; i += DEC_THREADS) {
        int k = i >> 6, n = i & 63;
        ((__half*)W2h)[n * 72 + k] = __float2half_rn(dw2[i]);
    }
    __syncthreads();

    // ---- strip-invariant per-thread fragments ----
    // pe fragments: rows (grp, grp+8), k-pairs (2rem,2rem+1) and (+8,+9) per k-chunk
    float2 peF[4][4];
    #pragma unroll
    for (int kit = 0; kit < 4; kit++) {
        int k = kit * 16 + 2 * rem;
        peF[kit][0] = *(const float2*)&pe_f[grp * 64 + k];
        peF[kit][1] = *(const float2*)&pe_f[(grp + 8) * 64 + k];
        peF[kit][2] = *(const float2*)&pe_f[grp * 64 + k + 8];
        peF[kit][3] = *(const float2*)&pe_f[(grp + 8) * 64 + k + 8];
    }
    // W1 B-fragments in registers (col n = nt*8+grp, k from rem)
    uint32_t w1f[4][8][2];
    #pragma unroll
    for (int kit = 0; kit < 4; kit++) {
        int k = kit * 16 + 2 * rem;
        #pragma unroll
        for (int nt = 0; nt < 8; nt++) {
            int n = nt * 8 + grp;
            w1f[kit][nt][0] = f2h2(dw1[k * 64 + n], dw1[(k + 1) * 64 + n]);
            w1f[kit][nt][1] = f2h2(dw1[(k + 8) * 64 + n], dw1[(k + 9) * 64 + n]);
        }
    }

    uint32_t* Hw = Hh + wid * 1152;      // this warp's H strip, pitch 36 u32
    float* zw = zb + wid * 128;

    int stride = gridDim.x * 8;
    int s = blockIdx.x * 8 + wid;
    if (s >= nstrips) return;

    float4 zcur = ((const float4*)(z + (size_t)s * 128))[lane];
    int ncur0 = g_n[2 * s], ncur1 = g_n[2 * s + 1];

    for (; s < nstrips; s += stride) {
        *(float4*)&zw[lane * 4] = zcur;
        int n0 = ncur0, n1 = ncur1;
        __syncwarp();

        // prefetch next strip
        int snext = s + stride;
        if (snext < nstrips) {
            zcur = ((const float4*)(z + (size_t)snext * 128))[lane];
            ncur0 = g_n[2 * snext];
            ncur1 = g_n[2 * snext + 1];
        }

        float C[2][8][4];
        #pragma unroll
        for (int mt = 0; mt < 2; mt++)
            #pragma unroll
            for (int nt = 0; nt < 8; nt++)
                #pragma unroll
                for (int q = 0; q < 4; q++) C[mt][nt][q] = 0.0f;

        // ---- GEMM1: A built inline (z broadcast LDS x pe regs), W1 from regs ----
        #pragma unroll
        for (int kit = 0; kit < 4; kit++) {
            int k0 = kit * 16;
            #pragma unroll
            for (int mt = 0; mt < 2; mt++) {
                float2 zlo = *(const float2*)&zw[mt * 64 + k0 + 2 * rem];
                float2 zhi = *(const float2*)&zw[mt * 64 + k0 + 2 * rem + 8];
                uint32_t a0 = f2h2(zlo.x * peF[kit][0].x, zlo.y * peF[kit][0].y);
                uint32_t a1 = f2h2(zlo.x * peF[kit][1].x, zlo.y * peF[kit][1].y);
                uint32_t a2 = f2h2(zhi.x * peF[kit][2].x, zhi.y * peF[kit][2].y);
                uint32_t a3 = f2h2(zhi.x * peF[kit][3].x, zhi.y * peF[kit][3].y);
                #pragma unroll
                for (int nt = 0; nt < 8; nt++)
                    mma_f16(C[mt][nt][0], C[mt][nt][1], C[mt][nt][2], C[mt][nt][3],
                            a0, a1, a2, a3, w1f[kit][nt][0], w1f[kit][nt][1]);
            }
        }

        // ---- epilogue1: bias + gelu -> half2 H in smem ----
        #pragma unroll
        for (int mt = 0; mt < 2; mt++) {
            #pragma unroll
            for (int nt = 0; nt < 8; nt++) {
                int col = nt * 8 + 2 * rem;
                float bx = b1s[col], by = b1s[col + 1];
                uint32_t h01 = f2h2(gelu_fast(C[mt][nt][0] + bx),
                                    gelu_fast(C[mt][nt][1] + by));
                uint32_t h23 = f2h2(gelu_fast(C[mt][nt][2] + bx),
                                    gelu_fast(C[mt][nt][3] + by));
                Hw[(mt * 16 + grp) * 36 + nt * 4 + rem] = h01;
                Hw[(mt * 16 + grp + 8) * 36 + nt * 4 + rem] = h23;
            }
        }
        __syncwarp();

        // ---- GEMM2: H (smem half) @ W2 (smem half) ----
        #pragma unroll
        for (int mt = 0; mt < 2; mt++)
            #pragma unroll
            for (int nt = 0; nt < 8; nt++)
                #pragma unroll
                for (int q = 0; q < 4; q++) C[mt][nt][q] = 0.0f;

        #pragma unroll
        for (int kit = 0; kit < 4; kit++) {
            uint32_t bf0[8], bf1[8];
            #pragma unroll
            for (int nt = 0; nt < 8; nt++) {
                int bi = (nt * 8 + grp) * 36 + kit * 8 + rem;
                bf0[nt] = W2h[bi];
                bf1[nt] = W2h[bi + 4];
            }
            #pragma unroll
            for (int mt = 0; mt < 2; mt++) {
                int ai = (mt * 16 + grp) * 36 + kit * 8 + rem;
                uint32_t a0 = Hw[ai];
                uint32_t a1 = Hw[ai + 8 * 36];
                uint32_t a2 = Hw[ai + 4];
                uint32_t a3 = Hw[ai + 8 * 36 + 4];
                #pragma unroll
                for (int nt = 0; nt < 8; nt++)
                    mma_f16(C[mt][nt][0], C[mt][nt][1], C[mt][nt][2], C[mt][nt][3],
                            a0, a1, a2, a3, bf0[nt], bf1[nt]);
            }
        }

        // ---- epilogue2: bias + mask + store ----
        #pragma unroll
        for (int mt = 0; mt < 2; mt++) {
            int nm = mt ? n1 : n0;
            bool v0 = grp < nm;
            bool v1 = grp + 8 < nm;
            int r0 = mt * 16 + grp;
            float* orow0 = out_x + ((size_t)s * 32 + r0) * DDIM;
            float* orow1 = orow0 + 8 * DDIM;
            #pragma unroll
            for (int nt = 0; nt < 8; nt++) {
                int col = nt * 8 + 2 * rem;
                float bx = b2s[col], by = b2s[col + 1];
                float2 lo, hi;
                lo.x = v0 ? (C[mt][nt][0] + bx) : 0.0f;
                lo.y = v0 ? (C[mt][nt][1] + by) : 0.0f;
                hi.x = v1 ? (C[mt][nt][2] + bx) : 0.0f;
                hi.y = v1 ? (C[mt][nt][3] + by) : 0.0f;
                *(float2*)(orow0 + col) = lo;
                *(float2*)(orow1 + col) = hi;
            }
        }
        __syncwarp();
    }
}

// ================= launch =================
extern "C" void kernel_launch(void* const* d_in, const int* in_sizes, int n_in,
                              void* d_out, int out_size) {
    const float* z      = (const float*)d_in[0];
    const float* sp_w1  = (const float*)d_in[1];
    const float* sp_b1  = (const float*)d_in[2];
    const float* sp_w2  = (const float*)d_in[3];
    const float* sp_b2  = (const float*)d_in[4];
    const float* pe_w1  = (const float*)d_in[5];
    const float* pe_b1  = (const float*)d_in[6];
    const float* pe_w2  = (const float*)d_in[7];
    const float* pe_b2  = (const float*)d_in[8];
    const float* dec_w1 = (const float*)d_in[9];
    const float* dec_b1 = (const float*)d_in[10];
    const float* dec_w2 = (const float*)d_in[11];
    const float* dec_b2 = (const float*)d_in[12];

    int B = in_sizes[0] / HDIM;   // 65536

    float* out = (float*)d_out;
    float* out_x     = out;                               // [B,16,64]
    float* out_mask  = out_x + (size_t)B * MAXN * DDIM;   // [B,16]
    float* out_batch = out_mask + (size_t)B * MAXN;       // [B,16]
    float* out_npred = out_batch + (size_t)B * MAXN;      // [B,16]

    static int nsm = 0;
    if (!nsm) {
        cudaDeviceGetAttribute(&nsm, cudaDevAttrMultiProcessorCount, 0);
        if (nsm <= 0) nsm = 148;
        cudaFuncSetAttribute(dec_kernel, cudaFuncAttributeMaxDynamicSharedMemorySize,
                             DEC_SMEM_BYTES);
    }

    sp_kernel<<<B / SP_ROWS, SP_ROWS>>>(z, sp_w1, sp_b1, sp_w2, sp_b2,
                                        out_npred, out_mask, out_batch);

    int nstrips = B / 2;   // 32768 strips of 32 rows
    dec_kernel<<<nsm, DEC_THREADS, DEC_SMEM_BYTES>>>(
        z, dec_w1, dec_b1, dec_w2, dec_b2,
        pe_w1, pe_b1, pe_w2, pe_b2, out_x, nstrips);
}